// round 15
// baseline (speedup 1.0000x reference)
#include <cuda_runtime.h>
#include <stdint.h>

// KVCache_9526237462719:
//   input_pos: int32[S], k_val/v_val: f32[B,H,S,D], k_cache/v_cache: f32[B,H,BLOCK,D]
//   out = [k_cache.at[:,:,pos].set(k_val)[:,:,:S,:], same for v] concat, f32.
//
// Strategy: the common/fast case (input_pos a full identity arange) makes the
// output exactly [k_val | v_val] contiguously -> two 64 MB D2D memcpys via the
// driver's optimized copy path (explicitly allowed + graph-capturable).
// A small fixup kernel afterward restores full generality: for any position p
// where input_pos[p] != p, it rewrites that position's K/V rows from the
// correct source (last-writer k_val/v_val row, or k_cache/v_cache if unwritten).
// For identity input the fixup reads 4 KB and exits.
#define KB      4
#define KH      32
#define KS      1024
#define KD      128
#define KBLOCK  4096

#define D4      (KD / 4)                 // 32 float4 per row
#define BH      (KB * KH)                // 128
#define HALF4   ((unsigned)BH * KS * D4) // 4,194,304 float4 per tensor
#define HALFBYTES ((size_t)HALF4 * 16)   // 64 MB

__global__ __launch_bounds__(256)
void kv_fixup_kernel(const int*    __restrict__ input_pos,
                     const float4* __restrict__ k_val,
                     const float4* __restrict__ v_val,
                     const float4* __restrict__ k_cache,
                     const float4* __restrict__ v_cache,
                     float4*       __restrict__ out) {
    int p = blockIdx.x * 256 + threadIdx.x;   // 4 blocks x 256 = KS threads
    if (p >= KS) return;

    // Fast exit: position p was written by source p (identity mapping).
    if (__ldg(input_pos + p) == p) return;

    // General path (not taken for identity input): find last writer of p.
    int s = -1;
    for (int t = 0; t < KS; t++) {
        if (__ldg(input_pos + t) == p) s = t;
    }

    // Rewrite all (bh, d4) elements of position p for both tensors.
    for (int bh = 0; bh < BH; bh++) {
        unsigned obase = ((unsigned)bh * KS + (unsigned)p) * D4;
        if (s >= 0) {
            unsigned ibase = ((unsigned)bh * KS + (unsigned)s) * D4;
            for (int d = 0; d < D4; d++) {
                out[obase + d]         = k_val[ibase + d];
                out[HALF4 + obase + d] = v_val[ibase + d];
            }
        } else {
            unsigned cbase = ((unsigned)bh * KBLOCK + (unsigned)p) * D4;
            for (int d = 0; d < D4; d++) {
                out[obase + d]         = k_cache[cbase + d];
                out[HALF4 + obase + d] = v_cache[cbase + d];
            }
        }
    }
}

extern "C" void kernel_launch(void* const* d_in, const int* in_sizes, int n_in,
                              void* d_out, int out_size) {
    const int*    input_pos = (const int*)d_in[0];
    const float4* k_val     = (const float4*)d_in[1];
    const float4* v_val     = (const float4*)d_in[2];
    const float4* k_cache   = (const float4*)d_in[3];
    const float4* v_cache   = (const float4*)d_in[4];
    float4*       out       = (float4*)d_out;

    // Bulk identity copy through the driver's optimized D2D path.
    cudaMemcpyAsync(out,         k_val, HALFBYTES, cudaMemcpyDeviceToDevice, 0);
    cudaMemcpyAsync(out + HALF4, v_val, HALFBYTES, cudaMemcpyDeviceToDevice, 0);

    // Generality fixup: rewrites any non-identity positions (no-op here).
    kv_fixup_kernel<<<(KS + 255) / 256, 256>>>(input_pos, k_val, v_val,
                                               k_cache, v_cache, out);
}

// round 16
// speedup vs baseline: 1.1073x; 1.1073x over previous
#include <cuda_runtime.h>
#include <stdint.h>

// KVCache_9526237462719 — FINAL (best measured: 43.49 us, R12):
//   input_pos: int32[S], k_val/v_val: f32[B,H,S,D], k_cache/v_cache: f32[B,H,BLOCK,D]
//   out = [k_cache.at[:,:,pos].set(k_val)[:,:,:S,:], same for v] concat, f32.
//
// Established by exhaustive search (11 structural variants, full load/store
// cache-policy matrix, memcpy-node executor swap):
//   - single pass is DRAM-bound: 268 MB mandatory traffic @ ~7.3 TB/s (91% of
//     spec) -> ~37 us kernel; ~6.5 us is fixed graph-replay overhead.
//   - default-policy loads (cross-replay L2 retention) are the only policy
//     that reaches the 43.5 us steady-state floor; store policy is neutral.
//   - no smem / no barriers: inv[p] resolved by a warp-uniform speculative
//     probe (input_pos[p] == p -> s = p) with a general fallback scan for
//     arbitrary permutations / partial coverage (never taken for this input).
#define KB      4
#define KH      32
#define KS      1024
#define KD      128
#define KBLOCK  4096

#define D4      (KD / 4)                 // 32 float4 per row
#define HALF4   (4u * KH * KS * D4)      // 4,194,304 = 2^22
#define TOTAL4  (2u * HALF4)             // 8,388,608 = 2^23

#define NTHREADS 512
#define NBLOCKS  8192                    // 8192*512 = 2^22 threads
#define STRIDE   (1u << 22)              // 2 slots * STRIDE = TOTAL4

__global__ __launch_bounds__(NTHREADS)
void kv_fused_kernel(const int*    __restrict__ input_pos,
                     const float4* __restrict__ k_val,
                     const float4* __restrict__ v_val,
                     const float4* __restrict__ k_cache,
                     const float4* __restrict__ v_cache,
                     float4*       __restrict__ out) {
    // i0 in [0, 2^22); slot 0 -> K half, slot 1 -> V half (compile-time).
    // d4, p, bh invariant across slots (2^22 is a multiple of S*D4 = 2^15).
    unsigned i0 = blockIdx.x * NTHREADS + threadIdx.x;
    unsigned d4 = i0 & (D4 - 1);
    unsigned r0 = i0 >> 5;
    unsigned p  = r0 & (KS - 1);
    unsigned bh = r0 >> 10;               // < 128

    // inv[p]: which source s wrote position p (−1 if none).
    int s;
    if (__ldg(input_pos + p) == (int)p) {
        s = (int)p;                       // fast path (always taken here)
    } else {
        s = -1;                           // general fallback: last writer wins
        for (int t = 0; t < KS; t++) {
            if (__ldg(input_pos + t) == (int)p) s = t;
        }
    }

    const float4* ksrc;
    const float4* vsrc;
    if (s >= 0) {
        size_t off = (size_t)(bh * (KS * D4) + (unsigned)s * D4 + d4);
        ksrc = k_val + off;
        vsrc = v_val + off;
    } else {
        size_t off = (size_t)(bh * (KBLOCK * D4) + p * D4 + d4);
        ksrc = k_cache + off;
        vsrc = v_cache + off;
    }

    // Default-policy loads and stores (maximize cross-replay L2 reuse).
    float4 rk = *ksrc;
    float4 rv = *vsrc;
    out[i0]          = rk;
    out[i0 + STRIDE] = rv;
}

extern "C" void kernel_launch(void* const* d_in, const int* in_sizes, int n_in,
                              void* d_out, int out_size) {
    const int*    input_pos = (const int*)d_in[0];
    const float4* k_val     = (const float4*)d_in[1];
    const float4* v_val     = (const float4*)d_in[2];
    const float4* k_cache   = (const float4*)d_in[3];
    const float4* v_cache   = (const float4*)d_in[4];
    float4*       out       = (float4*)d_out;

    kv_fused_kernel<<<NBLOCKS, NTHREADS>>>(input_pos, k_val, v_val,
                                           k_cache, v_cache, out);
}